// round 12
// baseline (speedup 1.0000x reference)
#include <cuda_runtime.h>

// WaveletLayer fused: db2 DWT -> scale -> inverse DWT -> ReLU, fully collapsed.
//
// QMF identity (hi[i] = (-1)^i lo[3-i]) collapses the chain to, per input
// pair (u,v) = (x[2m], x[2m+1]), with t = sqrt(3)/4:
//   p = 0.75u - t*v,  q = u - p
//   r = 0.25v - t*u,  s = v - r
//   out[2m]   = relu(k[m]*p + k[m+1]*q)
//   out[2m+1] = relu(k[m]*r + k[m+1]*s)
// Boundary/padding contributions cancel identically.
//
// R12 = R11 memory shape (ldcs x, stcs out, K LDG + shfl dedup) inside a
// SIMPLE persistent loop: 1184 blocks (8/SM) x 256 threads, each striding
// over the 8192 half-row tiles. No double-buffer (that cost R7 its
// occupancy), no syncs: warps desynchronize across iterations, spreading
// load bursts in time -> DRAM busy% rises instead of idling 36% between
// per-wave bursts. 32-bit offsets + __launch_bounds__(256,8) keep regs<=32
// so all 8 blocks stay resident.

#define NCOL  4096
#define LOUT  2049
#define NT    256
#define TILES 8192
#define GRID  1184   // 8 blocks/SM x 148 SMs
#define FULL  0xffffffffu

__global__ __launch_bounds__(NT, 8) void wavelet_fused_kernel(
    const float* __restrict__ x,
    const float* __restrict__ kern,
    float* __restrict__ out)
{
    const int tid  = threadIdx.x;
    const int lane = tid & 31;

    for (int t = blockIdx.x; t < TILES; t += GRID) {
        const int row  = t >> 1;
        const int m0   = ((t & 1) * NT + tid) * 4;   // first pair index
        const int xoff = row * NCOL + 2 * m0;        // fits in int32
        const int w    = row * LOUT + m0;
        const int d    = w & 3;                      // block-uniform

        // x[.. ..+7]: two aligned evict-first float4 loads
        const float4* x4 = reinterpret_cast<const float4*>(x + xoff);
        float4 X0 = __ldcs(x4);
        float4 X1 = __ldcs(x4 + 1);

        // K window K[m0..m0+4]: aligned cover [w-d, w-d+8). Adjacent lanes'
        // aligned pointers differ by one float4, so F1(lane) = F0(lane+1):
        // one LDG + 4 shfl; lane 31 loads F1 directly.
        // (Tail-safe: last row has d=3, F1 ends exactly at kern's last elem.)
        const float4* kp = reinterpret_cast<const float4*>(kern + (w - d));
        float4 F0 = kp[0];
        float4 F1;
        F1.x = __shfl_down_sync(FULL, F0.x, 1);
        F1.y = __shfl_down_sync(FULL, F0.y, 1);
        F1.z = __shfl_down_sync(FULL, F0.z, 1);
        F1.w = __shfl_down_sync(FULL, F0.w, 1);
        if (lane == 31) F1 = kp[1];

        float k0, k1, k2, k3, k4;
        if (d == 0)      { k0 = F0.x; k1 = F0.y; k2 = F0.z; k3 = F0.w; k4 = F1.x; }
        else if (d == 1) { k0 = F0.y; k1 = F0.z; k2 = F0.w; k3 = F1.x; k4 = F1.y; }
        else if (d == 2) { k0 = F0.z; k1 = F0.w; k2 = F1.x; k3 = F1.y; k4 = F1.z; }
        else             { k0 = F0.w; k1 = F1.x; k2 = F1.y; k3 = F1.z; k4 = F1.w; }

        const float T = 0.43301270189221932f;  // sqrt(3)/4

        float u, v, p, q, rr, ss;
        float4 r0, r1;

        u = X0.x; v = X0.y;
        p = fmaf(-T, v, 0.75f * u); q = u - p;
        rr = fmaf(-T, u, 0.25f * v); ss = v - rr;
        r0.x = fmaxf(fmaf(k1, q,  k0 * p),  0.0f);
        r0.y = fmaxf(fmaf(k1, ss, k0 * rr), 0.0f);

        u = X0.z; v = X0.w;
        p = fmaf(-T, v, 0.75f * u); q = u - p;
        rr = fmaf(-T, u, 0.25f * v); ss = v - rr;
        r0.z = fmaxf(fmaf(k2, q,  k1 * p),  0.0f);
        r0.w = fmaxf(fmaf(k2, ss, k1 * rr), 0.0f);

        u = X1.x; v = X1.y;
        p = fmaf(-T, v, 0.75f * u); q = u - p;
        rr = fmaf(-T, u, 0.25f * v); ss = v - rr;
        r1.x = fmaxf(fmaf(k3, q,  k2 * p),  0.0f);
        r1.y = fmaxf(fmaf(k3, ss, k2 * rr), 0.0f);

        u = X1.z; v = X1.w;
        p = fmaf(-T, v, 0.75f * u); q = u - p;
        rr = fmaf(-T, u, 0.25f * v); ss = v - rr;
        r1.z = fmaxf(fmaf(k4, q,  k3 * p),  0.0f);
        r1.w = fmaxf(fmaf(k4, ss, k3 * rr), 0.0f);

        float4* o4 = reinterpret_cast<float4*>(out + xoff);
        __stcs(o4,     r0);
        __stcs(o4 + 1, r1);
    }
}

extern "C" void kernel_launch(void* const* d_in, const int* in_sizes, int n_in,
                              void* d_out, int out_size)
{
    const float* x    = (const float*)d_in[0];
    const float* kern = (const float*)d_in[1];
    float*       out  = (float*)d_out;

    wavelet_fused_kernel<<<GRID, NT>>>(x, kern, out);
}